// round 1
// baseline (speedup 1.0000x reference)
#include <cuda_runtime.h>

#define B_    4
#define NH_   4
#define N_    1000
#define NF_   256
#define K_TOP 10
#define R_    (N_*K_TOP)
#define NODES (B_*N_)      // 4000
#define EDGES (B_*R_)      // 40000

// ---- scratch layout (floats) ----
#define OFF_SCUR 0            // 12000
#define OFF_ACUR 12000        // 4000
#define OFF_PEIN 16000        // 64000
#define OFF_FLAG 80000        // 40000
#define OFF_REIN 120000       // 200000
#define OFF_PEH  320000       // 1024000
#define OFF_PE   1344000      // 1024000
#define OFF_H1   2368000      // 10240000
#define OFF_H2   12608000     // 10240000
#define OFF_RENC 22848000     // 10240000
#define OFF_BASE 33088000     // 10240000
#define OFF_G2   43328000     // 1024000
#define OFF_G3   44352000     // 1024000
#define OFF_AGG  45376000     // 1024000
#define OFF_PPC  46400000     // 1024000
#define OFF_HOUT 47424000     // 1024000
#define SCRATCH_TOTAL 48448000

__device__ float g_scratch[SCRATCH_TOTAL];
__device__ int   g_send[EDGES];

// ---------------------------------------------------------------------------
// prep: s_cur, a_cur, pe_in = [sd(12), a(4)]
// ---------------------------------------------------------------------------
__global__ void prep_kernel(const float* __restrict__ a_hist,
                            const float* __restrict__ s_hist,
                            const float* __restrict__ s_delta,
                            float* __restrict__ scur, float* __restrict__ acur,
                            float* __restrict__ pein)
{
    int idx = blockIdx.x * blockDim.x + threadIdx.x;
    if (idx >= NODES) return;
    int b = idx / N_, n = idx % N_;
    acur[idx] = a_hist[(b*NH_ + NH_-1)*N_ + n];
    const float* sh = s_hist + ((size_t)(b*NH_ + NH_-1)*N_ + n)*3;
    scur[idx*3+0]=sh[0]; scur[idx*3+1]=sh[1]; scur[idx*3+2]=sh[2];
    float* pp = pein + (size_t)idx*16;
#pragma unroll
    for (int h=0; h<NH_; ++h) {
        const float* sd = s_delta + ((size_t)(b*NH_+h)*N_ + n)*3;
        pp[h*3+0]=sd[0]; pp[h*3+1]=sd[1]; pp[h*3+2]=sd[2];
        pp[12+h] = a_hist[(b*NH_+h)*N_ + n];
    }
}

// ---------------------------------------------------------------------------
// top-10 nearest (stable tie-break: lower index first, matching lax.top_k)
// ---------------------------------------------------------------------------
__global__ void topk_kernel(const float* __restrict__ scur,
                            const float* __restrict__ acur,
                            int* __restrict__ send, float* __restrict__ flag)
{
    __shared__ float sx[N_], sy[N_], sz[N_];
    __shared__ unsigned char st[N_];
    int b = blockIdx.y;
    for (int j = threadIdx.x; j < N_; j += blockDim.x) {
        int g = b*N_+j;
        sx[j]=scur[g*3+0]; sy[j]=scur[g*3+1]; sz[j]=scur[g*3+2];
        st[j] = acur[g] > 0.5f ? 1 : 0;
    }
    __syncthreads();
    int i = blockIdx.x*blockDim.x + threadIdx.x;
    if (i >= N_) return;
    bool ti = st[i] != 0;
    float xi=sx[i], yi=sy[i], zi=sz[i];
    float dv[K_TOP]; int iv[K_TOP];
#pragma unroll
    for (int t=0;t<K_TOP;++t){ dv[t]=3.0e38f; iv[t]=0; }
    for (int j=0;j<N_;++j) {
        float dx=__fadd_rn(xi,-sx[j]), dy=__fadd_rn(yi,-sy[j]), dz=__fadd_rn(zi,-sz[j]);
        float d = __fadd_rn(__fadd_rn(__fmul_rn(dx,dx),__fmul_rn(dy,dy)),__fmul_rn(dz,dz));
        if (ti && st[j]) d = 1e10f;
        if (d < dv[K_TOP-1]) {
#pragma unroll
            for (int t=K_TOP-1; t>=1; --t) {
                if (d < dv[t-1])      { dv[t]=dv[t-1]; iv[t]=iv[t-1]; }
                else if (d < dv[t])   { dv[t]=d;       iv[t]=j; }
            }
            if (d < dv[0]) { dv[0]=d; iv[0]=j; }
        }
    }
    int gi = b*N_ + i;
#pragma unroll
    for (int k=0;k<K_TOP;++k) {
        int rg = gi*K_TOP + k;
        send[rg] = b*N_ + iv[k];
        flag[rg] = (!ti && dv[k] < 0.25f) ? 1.0f : 0.0f;
    }
}

// ---------------------------------------------------------------------------
// re_in = [a_r, a_s, s_r - s_s] * flag  (5 cols)
// ---------------------------------------------------------------------------
__global__ void rein_kernel(const float* __restrict__ scur, const float* __restrict__ acur,
                            const int* __restrict__ send, const float* __restrict__ flag,
                            float* __restrict__ rein)
{
    int r = blockIdx.x*blockDim.x+threadIdx.x;
    if (r >= EDGES) return;
    int recv = r / K_TOP;      // global node index (r = (b*N+i)*10+k)
    int s = send[r];
    float f = flag[r];
    float* o = rein + (size_t)r*5;
    o[0] = f*acur[recv];
    o[1] = f*acur[s];
    o[2] = f*(scur[recv*3+0]-scur[s*3+0]);
    o[3] = f*(scur[recv*3+1]-scur[s*3+1]);
    o[4] = f*(scur[recv*3+2]-scur[s*3+2]);
}

// ---------------------------------------------------------------------------
// generic SGEMM: C = act(A[M,K] @ W[K,NOUT] + bias + add0 + add1)
// 64x64 tile, BK=16, 256 threads, 4x4 per thread
// ---------------------------------------------------------------------------
__global__ void __launch_bounds__(256)
gemm_kernel(const float* __restrict__ A, const float* __restrict__ W,
            const float* __restrict__ bias,
            const float* __restrict__ add0, const float* __restrict__ add1,
            float* __restrict__ C, int M, int K, int NOUT, int relu)
{
    __shared__ __align__(16) float As[16][64];
    __shared__ __align__(16) float Bs[16][64];
    int tid = threadIdx.x;
    int bm = blockIdx.x * 64;
    int bn = blockIdx.y * 64;
    int ty = tid >> 4, tx = tid & 15;

    float acc[4][4] = {};
    int la_row = tid >> 2;          // 0..63
    int la_k0  = (tid & 3) * 4;     // 0,4,8,12

    for (int k0 = 0; k0 < K; k0 += 16) {
        int gm = bm + la_row;
#pragma unroll
        for (int q = 0; q < 4; ++q) {
            int kk = la_k0 + q;
            int gk = k0 + kk;
            float v = (gm < M && gk < K) ? A[(size_t)gm * K + gk] : 0.f;
            As[kk][la_row] = v;
        }
#pragma unroll
        for (int q = 0; q < 4; ++q) {
            int lin = tid + q * 256;
            int kk = lin >> 6;
            int nn = lin & 63;
            int gk = k0 + kk;
            float v = (gk < K) ? W[(size_t)gk * NOUT + bn + nn] : 0.f;
            Bs[kk][nn] = v;
        }
        __syncthreads();
#pragma unroll
        for (int kk = 0; kk < 16; ++kk) {
            float4 a4 = *(const float4*)&As[kk][ty*4];
            float4 b4 = *(const float4*)&Bs[kk][tx*4];
            float av[4] = {a4.x,a4.y,a4.z,a4.w};
            float bv[4] = {b4.x,b4.y,b4.z,b4.w};
#pragma unroll
            for (int i=0;i<4;++i)
#pragma unroll
                for (int j=0;j<4;++j)
                    acc[i][j] = fmaf(av[i], bv[j], acc[i][j]);
        }
        __syncthreads();
    }
#pragma unroll
    for (int i=0;i<4;++i) {
        int gm = bm + ty*4 + i;
        if (gm >= M) continue;
#pragma unroll
        for (int j=0;j<4;++j) {
            int gn = bn + tx*4 + j;
            float v = acc[i][j];
            if (bias) v += bias[gn];
            size_t off = (size_t)gm * NOUT + gn;
            if (add0) v += add0[off];
            if (add1) v += add1[off];
            if (relu) v = fmaxf(v, 0.f);
            C[off] = v;
        }
    }
}

// ---------------------------------------------------------------------------
// agg[n,c] = sum_k flag * relu(base[n*10+k,c] + G2[n,c] + G3[send,c])
// ---------------------------------------------------------------------------
__global__ void agg_kernel(const float* __restrict__ base, const float* __restrict__ G2,
                           const float* __restrict__ G3, const int* __restrict__ send,
                           const float* __restrict__ flag, float* __restrict__ agg)
{
    int node = blockIdx.x;
    int c = threadIdx.x;
    float g2 = G2[(size_t)node*NF_ + c];
    float acc = 0.f;
#pragma unroll
    for (int k=0;k<K_TOP;++k) {
        int r = node*K_TOP + k;
        if (flag[r] != 0.f) {
            float v = base[(size_t)r*NF_ + c] + g2 + G3[(size_t)send[r]*NF_ + c];
            acc += fmaxf(v, 0.f);
        }
    }
    agg[(size_t)node*NF_ + c] = acc;
}

// ---------------------------------------------------------------------------
// out = h @ pr_w1 + pr_b1 + s_cur   (256 -> 3)
// ---------------------------------------------------------------------------
__global__ void out_kernel(const float* __restrict__ h, const float* __restrict__ w,
                           const float* __restrict__ bias, const float* __restrict__ scur,
                           float* __restrict__ out)
{
    int e = blockIdx.x*blockDim.x+threadIdx.x;
    if (e >= NODES*3) return;
    int row = e/3, j = e%3;
    float acc = 0.f;
    const float* hr = h + (size_t)row*NF_;
#pragma unroll 8
    for (int k=0;k<NF_;++k) acc = fmaf(hr[k], w[k*3+j], acc);
    out[e] = acc + bias[j] + scur[e];
}

// ---------------------------------------------------------------------------
extern "C" void kernel_launch(void* const* d_in, const int* in_sizes, int n_in,
                              void* d_out, int out_size)
{
    const float* a_hist =(const float*)d_in[0];
    const float* s_hist =(const float*)d_in[1];
    const float* s_delta=(const float*)d_in[2];
    const float* pe_w0=(const float*)d_in[3];  const float* pe_b0=(const float*)d_in[4];
    const float* pe_w1=(const float*)d_in[5];  const float* pe_b1=(const float*)d_in[6];
    const float* re_w0=(const float*)d_in[7];  const float* re_b0=(const float*)d_in[8];
    const float* re_w1=(const float*)d_in[9];  const float* re_b1=(const float*)d_in[10];
    const float* re_w2=(const float*)d_in[11]; const float* re_b2=(const float*)d_in[12];
    const float* rp_w =(const float*)d_in[13]; const float* rp_b =(const float*)d_in[14];
    const float* pp_w =(const float*)d_in[15]; const float* pp_b =(const float*)d_in[16];
    const float* pr_w0=(const float*)d_in[17]; const float* pr_b0=(const float*)d_in[18];
    const float* pr_w1=(const float*)d_in[19]; const float* pr_b1=(const float*)d_in[20];
    float* out = (float*)d_out;

    void* sp;  cudaGetSymbolAddress(&sp, g_scratch);
    void* ipp; cudaGetSymbolAddress(&ipp, g_send);
    float* S = (float*)sp;
    int* send = (int*)ipp;

    float* scur=S+OFF_SCUR; float* acur=S+OFF_ACUR; float* pein=S+OFF_PEIN;
    float* flag=S+OFF_FLAG; float* rein=S+OFF_REIN; float* peh=S+OFF_PEH;
    float* pe  =S+OFF_PE;   float* h1  =S+OFF_H1;   float* h2  =S+OFF_H2;
    float* renc=S+OFF_RENC; float* base=S+OFF_BASE; float* G2  =S+OFF_G2;
    float* G3  =S+OFF_G3;   float* agg =S+OFF_AGG;  float* ppc =S+OFF_PPC;
    float* hout=S+OFF_HOUT;

    prep_kernel<<<(NODES+127)/128,128>>>(a_hist,s_hist,s_delta,scur,acur,pein);
    topk_kernel<<<dim3((N_+127)/128,B_),128>>>(scur,acur,send,flag);
    rein_kernel<<<(EDGES+255)/256,256>>>(scur,acur,send,flag,rein);

    auto GEMM = [&](const float* A,const float* W,const float* bias,
                    const float* a0,const float* a1,float* C,int M,int K,int relu){
        dim3 grid((M+63)/64, NF_/64);
        gemm_kernel<<<grid,256>>>(A,W,bias,a0,a1,C,M,K,NF_,relu);
    };

    // particle encoder
    GEMM(pein, pe_w0, pe_b0, nullptr, nullptr, peh, NODES, 16, 1);
    GEMM(peh,  pe_w1, pe_b1, nullptr, nullptr, pe,  NODES, 256, 1);
    // relation encoder (all edges)
    GEMM(rein, re_w0, re_b0, nullptr, nullptr, h1,   EDGES, 5,   1);
    GEMM(h1,   re_w1, re_b1, nullptr, nullptr, h2,   EDGES, 256, 1);
    GEMM(h2,   re_w2, re_b2, nullptr, nullptr, renc, EDGES, 256, 1);
    // base = renc @ rp_w[0:256] + rp_b  (constant over psteps)
    GEMM(renc, rp_w,  rp_b,  nullptr, nullptr, base, EDGES, 256, 0);
    // ppc = particle_encode @ pp_w[0:256] + pp_b  (constant over psteps)
    GEMM(pe,   pp_w,  pp_b,  nullptr, nullptr, ppc,  NODES, 256, 0);

    for (int step=0; step<3; ++step) {
        GEMM(pe, rp_w + 256*NF_, nullptr, nullptr, nullptr, G2, NODES, 256, 0);
        GEMM(pe, rp_w + 512*NF_, nullptr, nullptr, nullptr, G3, NODES, 256, 0);
        agg_kernel<<<NODES, NF_>>>(base, G2, G3, send, flag, agg);
        // PE = relu(ppc + agg @ pp_w[256:512] + PE)   (in-place elementwise safe)
        GEMM(agg, pp_w + 256*NF_, nullptr, ppc, pe, pe, NODES, 256, 1);
    }

    GEMM(pe, pr_w0, pr_b0, nullptr, nullptr, hout, NODES, 256, 1);
    out_kernel<<<(NODES*3+127)/128,128>>>(hout, pr_w1, pr_b1, scur, out);
}

// round 2
// speedup vs baseline: 1.5932x; 1.5932x over previous
#include <cuda_runtime.h>

#define B_    4
#define NH_   4
#define N_    1000
#define NF_   256
#define K_TOP 10
#define R_    (N_*K_TOP)
#define NODES (B_*N_)      // 4000
#define EDGES (B_*R_)      // 40000

// ---- scratch layout (floats) ----
#define OFF_SCUR 0
#define OFF_ACUR (OFF_SCUR + 12000)
#define OFF_PEIN (OFF_ACUR + 4000)
#define OFF_FLAG (OFF_PEIN + 64000)
#define OFF_REIN (OFF_FLAG + 40000)
#define OFF_BUFA (OFF_REIN + EDGES*5)
#define OFF_BUFB (OFF_BUFA + EDGES*NF_)
#define OFF_BASE (OFF_BUFB + EDGES*NF_)
#define OFF_PEH  (OFF_BASE + EDGES*NF_)
#define OFF_PE   (OFF_PEH  + NODES*NF_)
#define OFF_G23  (OFF_PE   + NODES*NF_)
#define OFF_AGG  (OFF_G23  + NODES*2*NF_)
#define OFF_PPC  (OFF_AGG  + NODES*NF_)
#define OFF_HOUT (OFF_PPC  + NODES*NF_)
#define OFF_W23  (OFF_HOUT + NODES*NF_)
#define SCRATCH_TOTAL (OFF_W23 + 2*NF_*NF_)

__device__ float g_scratch[SCRATCH_TOTAL];
__device__ int   g_send[EDGES];
__device__ int   g_sendc[EDGES];
__device__ int   g_offsets[NODES+1];
__device__ int   g_Mact[1];

// ---------------------------------------------------------------------------
__global__ void prep_kernel(const float* __restrict__ a_hist,
                            const float* __restrict__ s_hist,
                            const float* __restrict__ s_delta,
                            float* __restrict__ scur, float* __restrict__ acur,
                            float* __restrict__ pein)
{
    int idx = blockIdx.x * blockDim.x + threadIdx.x;
    if (idx >= NODES) return;
    int b = idx / N_, n = idx % N_;
    acur[idx] = a_hist[(b*NH_ + NH_-1)*N_ + n];
    const float* sh = s_hist + ((size_t)(b*NH_ + NH_-1)*N_ + n)*3;
    scur[idx*3+0]=sh[0]; scur[idx*3+1]=sh[1]; scur[idx*3+2]=sh[2];
    float* pp = pein + (size_t)idx*16;
#pragma unroll
    for (int h=0; h<NH_; ++h) {
        const float* sd = s_delta + ((size_t)(b*NH_+h)*N_ + n)*3;
        pp[h*3+0]=sd[0]; pp[h*3+1]=sd[1]; pp[h*3+2]=sd[2];
        pp[12+h] = a_hist[(b*NH_+h)*N_ + n];
    }
}

// ---------------------------------------------------------------------------
// top-10 nearest (stable tie-break matching lax.top_k)
// ---------------------------------------------------------------------------
__global__ void topk_kernel(const float* __restrict__ scur,
                            const float* __restrict__ acur,
                            int* __restrict__ send, float* __restrict__ flag)
{
    __shared__ float sx[N_], sy[N_], sz[N_];
    __shared__ unsigned char st[N_];
    int b = blockIdx.y;
    for (int j = threadIdx.x; j < N_; j += blockDim.x) {
        int g = b*N_+j;
        sx[j]=scur[g*3+0]; sy[j]=scur[g*3+1]; sz[j]=scur[g*3+2];
        st[j] = acur[g] > 0.5f ? 1 : 0;
    }
    __syncthreads();
    int i = blockIdx.x*blockDim.x + threadIdx.x;
    if (i >= N_) return;
    bool ti = st[i] != 0;
    float xi=sx[i], yi=sy[i], zi=sz[i];
    float dv[K_TOP]; int iv[K_TOP];
#pragma unroll
    for (int t=0;t<K_TOP;++t){ dv[t]=3.0e38f; iv[t]=0; }
    for (int j=0;j<N_;++j) {
        float dx=__fadd_rn(xi,-sx[j]), dy=__fadd_rn(yi,-sy[j]), dz=__fadd_rn(zi,-sz[j]);
        float d = __fadd_rn(__fadd_rn(__fmul_rn(dx,dx),__fmul_rn(dy,dy)),__fmul_rn(dz,dz));
        if (ti && st[j]) d = 1e10f;
        if (d < dv[K_TOP-1]) {
#pragma unroll
            for (int t=K_TOP-1; t>=1; --t) {
                if (d < dv[t-1])      { dv[t]=dv[t-1]; iv[t]=iv[t-1]; }
                else if (d < dv[t])   { dv[t]=d;       iv[t]=j; }
            }
            if (d < dv[0]) { dv[0]=d; iv[0]=j; }
        }
    }
    int gi = b*N_ + i;
#pragma unroll
    for (int k=0;k<K_TOP;++k) {
        int rg = gi*K_TOP + k;
        send[rg] = b*N_ + iv[k];
        flag[rg] = (!ti && dv[k] < 0.25f) ? 1.0f : 0.0f;
    }
}

// ---------------------------------------------------------------------------
// single-block exclusive scan of per-node active-edge counts
// ---------------------------------------------------------------------------
__global__ void __launch_bounds__(1024)
scan_kernel(const float* __restrict__ flag, int* __restrict__ offsets,
            int* __restrict__ Mact)
{
    __shared__ int part[1024];
    int tid = threadIdx.x;
    int cnt[4], local[4];
    int run = 0;
#pragma unroll
    for (int q=0;q<4;++q) {
        int node = tid*4+q;
        int c = 0;
        if (node < NODES) {
#pragma unroll
            for (int k=0;k<K_TOP;++k) c += (flag[node*K_TOP+k] != 0.f);
        }
        cnt[q]=c; local[q]=run; run+=c;
    }
    part[tid]=run;
    __syncthreads();
    for (int d=1; d<1024; d<<=1) {
        int v = (tid>=d) ? part[tid-d] : 0;
        __syncthreads();
        part[tid] += v;
        __syncthreads();
    }
    int before = (tid==0) ? 0 : part[tid-1];
#pragma unroll
    for (int q=0;q<4;++q) {
        int node = tid*4+q;
        if (node < NODES) offsets[node] = before + local[q];
    }
    if (tid == 1023) { offsets[NODES] = part[1023]; Mact[0] = part[1023]; }
    (void)cnt;
}

// ---------------------------------------------------------------------------
// compact fill: write rein rows + sendc for active edges, node-ordered
// ---------------------------------------------------------------------------
__global__ void fill_kernel(const float* __restrict__ scur, const float* __restrict__ acur,
                            const int* __restrict__ send, const float* __restrict__ flag,
                            const int* __restrict__ offsets,
                            int* __restrict__ sendc, float* __restrict__ rein)
{
    int node = blockIdx.x*blockDim.x+threadIdx.x;
    if (node >= NODES) return;
    int pos = offsets[node];
    float ar = acur[node];
    float x = scur[node*3+0], y = scur[node*3+1], z = scur[node*3+2];
#pragma unroll
    for (int k=0;k<K_TOP;++k) {
        int r = node*K_TOP+k;
        if (flag[r] != 0.f) {
            int s = send[r];
            sendc[pos] = s;
            float* o = rein + (size_t)pos*5;
            o[0] = ar;
            o[1] = acur[s];
            o[2] = x - scur[s*3+0];
            o[3] = y - scur[s*3+1];
            o[4] = z - scur[s*3+2];
            pos++;
        }
    }
}

// ---------------------------------------------------------------------------
// W23 = concat columns of rp_w[256:512,:] and rp_w[512:768,:]  -> (256, 512)
// ---------------------------------------------------------------------------
__global__ void w23_kernel(const float* __restrict__ rp_w, float* __restrict__ w23)
{
    int idx = blockIdx.x*blockDim.x+threadIdx.x;
    if (idx >= NF_*2*NF_) return;
    int k = idx / (2*NF_), c = idx % (2*NF_);
    float v = (c < NF_) ? rp_w[(256+k)*NF_ + c] : rp_w[(512+k)*NF_ + (c-NF_)];
    w23[idx] = v;
}

// ---------------------------------------------------------------------------
// 64x64 tile SGEMM (node-level GEMMs; latency-bound regime)
// ---------------------------------------------------------------------------
__global__ void __launch_bounds__(256)
gemm64(const float* __restrict__ A, const float* __restrict__ W,
       const float* __restrict__ bias,
       const float* __restrict__ add0, const float* __restrict__ add1,
       float* __restrict__ C, int M, int K, int NOUT, int relu)
{
    __shared__ __align__(16) float As[16][64];
    __shared__ __align__(16) float Bs[16][64];
    int tid = threadIdx.x;
    int bm = blockIdx.x * 64;
    int bn = blockIdx.y * 64;
    int ty = tid >> 4, tx = tid & 15;
    float acc[4][4] = {};
    int la_row = tid >> 2;
    int la_k0  = (tid & 3) * 4;

    for (int k0 = 0; k0 < K; k0 += 16) {
        int gm = bm + la_row;
#pragma unroll
        for (int q = 0; q < 4; ++q) {
            int kk = la_k0 + q;
            int gk = k0 + kk;
            As[kk][la_row] = (gm < M && gk < K) ? A[(size_t)gm * K + gk] : 0.f;
        }
#pragma unroll
        for (int q = 0; q < 4; ++q) {
            int lin = tid + q * 256;
            int kk = lin >> 6;
            int nn = lin & 63;
            int gk = k0 + kk;
            Bs[kk][nn] = (gk < K) ? W[(size_t)gk * NOUT + bn + nn] : 0.f;
        }
        __syncthreads();
#pragma unroll
        for (int kk = 0; kk < 16; ++kk) {
            float4 a4 = *(const float4*)&As[kk][ty*4];
            float4 b4 = *(const float4*)&Bs[kk][tx*4];
            float av[4] = {a4.x,a4.y,a4.z,a4.w};
            float bv[4] = {b4.x,b4.y,b4.z,b4.w};
#pragma unroll
            for (int i=0;i<4;++i)
#pragma unroll
                for (int j=0;j<4;++j)
                    acc[i][j] = fmaf(av[i], bv[j], acc[i][j]);
        }
        __syncthreads();
    }
#pragma unroll
    for (int i=0;i<4;++i) {
        int gm = bm + ty*4 + i;
        if (gm >= M) continue;
#pragma unroll
        for (int j=0;j<4;++j) {
            int gn = bn + tx*4 + j;
            float v = acc[i][j];
            if (bias) v += bias[gn];
            size_t off = (size_t)gm * NOUT + gn;
            if (add0) v += add0[off];
            if (add1) v += add1[off];
            if (relu) v = fmaxf(v, 0.f);
            C[off] = v;
        }
    }
}

// ---------------------------------------------------------------------------
// 128x128x16 double-buffered SGEMM, dynamic M via device pointer
// ---------------------------------------------------------------------------
__global__ void __launch_bounds__(256, 2)
gemm128(const float* __restrict__ A, const float* __restrict__ W,
        const float* __restrict__ bias, float* __restrict__ C,
        const int* __restrict__ Mp, int K, int NOUT, int relu)
{
    int M = __ldg(Mp);
    int bm = blockIdx.x * 128;
    if (bm >= M) return;
    int bn = blockIdx.y * 128;

    __shared__ __align__(16) float As[2][16][128];
    __shared__ __align__(16) float Bs[2][16][128];

    int tid = threadIdx.x;
    int tx = tid & 15, ty = tid >> 4;
    float acc[8][8] = {};

    const bool k_vec = (K % 4 == 0);
    int nk = (K + 15) / 16;

#define LOAD_TILE(buf, k0)                                                     \
    {                                                                          \
        _Pragma("unroll")                                                      \
        for (int i = 0; i < 2; ++i) {                                          \
            int idx = tid + i * 256;                                           \
            int row = idx >> 2, kq = (idx & 3) * 4;                            \
            int gm = bm + row;                                                 \
            float4 v = make_float4(0.f, 0.f, 0.f, 0.f);                        \
            if (gm < M) {                                                      \
                if (k_vec && (k0) + kq + 3 < K) {                              \
                    v = *(const float4*)(A + (size_t)gm * K + (k0) + kq);      \
                } else {                                                       \
                    float t0 = ((k0)+kq+0 < K) ? A[(size_t)gm*K+(k0)+kq+0] : 0.f; \
                    float t1 = ((k0)+kq+1 < K) ? A[(size_t)gm*K+(k0)+kq+1] : 0.f; \
                    float t2 = ((k0)+kq+2 < K) ? A[(size_t)gm*K+(k0)+kq+2] : 0.f; \
                    float t3 = ((k0)+kq+3 < K) ? A[(size_t)gm*K+(k0)+kq+3] : 0.f; \
                    v = make_float4(t0, t1, t2, t3);                           \
                }                                                              \
            }                                                                  \
            As[buf][kq+0][row] = v.x; As[buf][kq+1][row] = v.y;                \
            As[buf][kq+2][row] = v.z; As[buf][kq+3][row] = v.w;                \
        }                                                                      \
        _Pragma("unroll")                                                      \
        for (int i = 0; i < 2; ++i) {                                          \
            int idx = tid + i * 256;                                           \
            int kk = idx >> 5, nn = (idx & 31) * 4;                            \
            float4 v = make_float4(0.f, 0.f, 0.f, 0.f);                        \
            if ((k0) + kk < K)                                                 \
                v = *(const float4*)(W + (size_t)((k0) + kk) * NOUT + bn + nn);\
            *(float4*)&Bs[buf][kk][nn] = v;                                    \
        }                                                                      \
    }

    LOAD_TILE(0, 0);
    __syncthreads();

    for (int t = 0; t < nk; ++t) {
        int cur = t & 1, nxt = cur ^ 1;
        if (t + 1 < nk) LOAD_TILE(nxt, (t + 1) * 16);
#pragma unroll
        for (int kk = 0; kk < 16; ++kk) {
            float a[8], b[8];
            *(float4*)&a[0] = *(const float4*)&As[cur][kk][ty*8];
            *(float4*)&a[4] = *(const float4*)&As[cur][kk][ty*8+4];
            *(float4*)&b[0] = *(const float4*)&Bs[cur][kk][tx*8];
            *(float4*)&b[4] = *(const float4*)&Bs[cur][kk][tx*8+4];
#pragma unroll
            for (int i = 0; i < 8; ++i)
#pragma unroll
                for (int j = 0; j < 8; ++j)
                    acc[i][j] = fmaf(a[i], b[j], acc[i][j]);
        }
        __syncthreads();
    }
#undef LOAD_TILE

#pragma unroll
    for (int i = 0; i < 8; ++i) {
        int gm = bm + ty*8 + i;
        if (gm >= M) continue;
        float* crow = C + (size_t)gm * NOUT + bn + tx*8;
        float v[8];
#pragma unroll
        for (int j = 0; j < 8; ++j) {
            float x = acc[i][j];
            if (bias) x += bias[bn + tx*8 + j];
            if (relu) x = fmaxf(x, 0.f);
            v[j] = x;
        }
        *(float4*)&crow[0] = make_float4(v[0],v[1],v[2],v[3]);
        *(float4*)&crow[4] = make_float4(v[4],v[5],v[6],v[7]);
    }
}

// ---------------------------------------------------------------------------
// agg[n,c] = sum over active edges of relu(base[e,c] + G2[n,c] + G3[send,c])
// ---------------------------------------------------------------------------
__global__ void agg_kernel(const float* __restrict__ base, const float* __restrict__ G23,
                           const int* __restrict__ sendc, const int* __restrict__ offsets,
                           float* __restrict__ agg)
{
    int node = blockIdx.x;
    int c = threadIdx.x;
    float g2 = G23[(size_t)node*(2*NF_) + c];
    int e0 = offsets[node], e1 = offsets[node+1];
    float acc = 0.f;
    for (int e = e0; e < e1; ++e) {
        float v = base[(size_t)e*NF_ + c] + g2 + G23[(size_t)sendc[e]*(2*NF_) + NF_ + c];
        acc += fmaxf(v, 0.f);
    }
    agg[(size_t)node*NF_ + c] = acc;
}

// ---------------------------------------------------------------------------
__global__ void out_kernel(const float* __restrict__ h, const float* __restrict__ w,
                           const float* __restrict__ bias, const float* __restrict__ scur,
                           float* __restrict__ out)
{
    int e = blockIdx.x*blockDim.x+threadIdx.x;
    if (e >= NODES*3) return;
    int row = e/3, j = e%3;
    float acc = 0.f;
    const float* hr = h + (size_t)row*NF_;
#pragma unroll 8
    for (int k=0;k<NF_;++k) acc = fmaf(hr[k], w[k*3+j], acc);
    out[e] = acc + bias[j] + scur[e];
}

// ---------------------------------------------------------------------------
extern "C" void kernel_launch(void* const* d_in, const int* in_sizes, int n_in,
                              void* d_out, int out_size)
{
    const float* a_hist =(const float*)d_in[0];
    const float* s_hist =(const float*)d_in[1];
    const float* s_delta=(const float*)d_in[2];
    const float* pe_w0=(const float*)d_in[3];  const float* pe_b0=(const float*)d_in[4];
    const float* pe_w1=(const float*)d_in[5];  const float* pe_b1=(const float*)d_in[6];
    const float* re_w0=(const float*)d_in[7];  const float* re_b0=(const float*)d_in[8];
    const float* re_w1=(const float*)d_in[9];  const float* re_b1=(const float*)d_in[10];
    const float* re_w2=(const float*)d_in[11]; const float* re_b2=(const float*)d_in[12];
    const float* rp_w =(const float*)d_in[13]; const float* rp_b =(const float*)d_in[14];
    const float* pp_w =(const float*)d_in[15]; const float* pp_b =(const float*)d_in[16];
    const float* pr_w0=(const float*)d_in[17]; const float* pr_b0=(const float*)d_in[18];
    const float* pr_w1=(const float*)d_in[19]; const float* pr_b1=(const float*)d_in[20];
    float* out = (float*)d_out;

    void* sp;   cudaGetSymbolAddress(&sp, g_scratch);
    void* p1;   cudaGetSymbolAddress(&p1, g_send);
    void* p2;   cudaGetSymbolAddress(&p2, g_sendc);
    void* p3;   cudaGetSymbolAddress(&p3, g_offsets);
    void* p4;   cudaGetSymbolAddress(&p4, g_Mact);
    float* S = (float*)sp;
    int* send    = (int*)p1;
    int* sendc   = (int*)p2;
    int* offsets = (int*)p3;
    int* Mact    = (int*)p4;

    float* scur=S+OFF_SCUR; float* acur=S+OFF_ACUR; float* pein=S+OFF_PEIN;
    float* flag=S+OFF_FLAG; float* rein=S+OFF_REIN;
    float* bufA=S+OFF_BUFA; float* bufB=S+OFF_BUFB; float* base=S+OFF_BASE;
    float* peh =S+OFF_PEH;  float* pe  =S+OFF_PE;   float* G23 =S+OFF_G23;
    float* agg =S+OFF_AGG;  float* ppc =S+OFF_PPC;  float* hout=S+OFF_HOUT;
    float* w23 =S+OFF_W23;

    prep_kernel<<<(NODES+127)/128,128>>>(a_hist,s_hist,s_delta,scur,acur,pein);
    topk_kernel<<<dim3((N_+127)/128,B_),128>>>(scur,acur,send,flag);
    scan_kernel<<<1,1024>>>(flag, offsets, Mact);
    fill_kernel<<<(NODES+127)/128,128>>>(scur,acur,send,flag,offsets,sendc,rein);
    w23_kernel<<<(NF_*2*NF_+255)/256,256>>>(rp_w, w23);

    auto G64 = [&](const float* A,const float* W,const float* bias,
                   const float* a0,const float* a1,float* C,int M,int K,int NOUT,int relu){
        dim3 grid((M+63)/64, NOUT/64);
        gemm64<<<grid,256>>>(A,W,bias,a0,a1,C,M,K,NOUT,relu);
    };
    auto G128E = [&](const float* A,const float* W,const float* bias,
                     float* C,int K,int relu){
        dim3 grid((EDGES+127)/128, NF_/128);   // fixed worst-case grid; early exit on Mact
        gemm128<<<grid,256>>>(A,W,bias,C,Mact,K,NF_,relu);
    };

    // particle encoder (node-level)
    G64(pein, pe_w0, pe_b0, nullptr, nullptr, peh, NODES, 16,  NF_, 1);
    G64(peh,  pe_w1, pe_b1, nullptr, nullptr, pe,  NODES, 256, NF_, 1);
    // ppc = particle_encode @ pp_w[0:256] + pp_b (loop-invariant)
    G64(pe,   pp_w,  pp_b,  nullptr, nullptr, ppc, NODES, 256, NF_, 0);

    // relation encoder on compacted edges
    G128E(rein, re_w0, re_b0, bufA, 5,   1);
    G128E(bufA, re_w1, re_b1, bufB, 256, 1);
    G128E(bufB, re_w2, re_b2, bufA, 256, 1);          // bufA = relation_encode
    G128E(bufA, rp_w,  rp_b,  base, 256, 0);          // base = renc@rp_w[0:256]+rp_b

    for (int step=0; step<3; ++step) {
        // G23 = pe @ [W2|W3]  (node-level, N=512)
        G64(pe, w23, nullptr, nullptr, nullptr, G23, NODES, 256, 2*NF_, 0);
        agg_kernel<<<NODES, NF_>>>(base, G23, sendc, offsets, agg);
        // pe = relu(ppc + agg @ pp_w[256:512] + pe)
        G64(agg, pp_w + 256*NF_, nullptr, ppc, pe, pe, NODES, 256, NF_, 1);
    }

    G64(pe, pr_w0, pr_b0, nullptr, nullptr, hout, NODES, 256, NF_, 1);
    out_kernel<<<(NODES*3+127)/128,128>>>(hout, pr_w1, pr_b1, scur, out);
}

// round 3
// speedup vs baseline: 2.4343x; 1.5280x over previous
#include <cuda_runtime.h>

#define B_    4
#define NH_   4
#define N_    1000
#define NF_   256
#define K_TOP 10
#define R_    (N_*K_TOP)
#define NODES (B_*N_)      // 4000
#define EDGES (B_*R_)      // 40000

// ---- scratch layout (floats) ----
#define OFF_SCUR 0
#define OFF_ACUR (OFF_SCUR + 12000)
#define OFF_PEIN (OFF_ACUR + 4000)
#define OFF_FLAG (OFF_PEIN + 64000)
#define OFF_REIN (OFF_FLAG + 40000)
#define OFF_BUFA (OFF_REIN + EDGES*5)
#define OFF_BUFB (OFF_BUFA + EDGES*NF_)
#define OFF_BASE (OFF_BUFB + EDGES*NF_)
#define OFF_PEH  (OFF_BASE + EDGES*NF_)
#define OFF_PE   (OFF_PEH  + NODES*NF_)
#define OFF_G23  (OFF_PE   + NODES*NF_)
#define OFF_AGG  (OFF_G23  + NODES*2*NF_)
#define OFF_PPC  (OFF_AGG  + NODES*NF_)
#define OFF_HOUT (OFF_PPC  + NODES*NF_)
#define OFF_W23  (OFF_HOUT + NODES*NF_)
#define SCRATCH_TOTAL (OFF_W23 + 2*NF_*NF_)

__device__ float g_scratch[SCRATCH_TOTAL];
__device__ int   g_send[EDGES];
__device__ int   g_sendc[EDGES];
__device__ int   g_offsets[NODES+1];
__device__ int   g_Mact[1];

__device__ __forceinline__ unsigned f2tf(float x) {
    unsigned r;
    asm("cvt.rna.tf32.f32 %0, %1;" : "=r"(r) : "f"(x));
    return r;
}

// ---------------------------------------------------------------------------
__global__ void prep_kernel(const float* __restrict__ a_hist,
                            const float* __restrict__ s_hist,
                            const float* __restrict__ s_delta,
                            float* __restrict__ scur, float* __restrict__ acur,
                            float* __restrict__ pein)
{
    int idx = blockIdx.x * blockDim.x + threadIdx.x;
    if (idx >= NODES) return;
    int b = idx / N_, n = idx % N_;
    acur[idx] = a_hist[(b*NH_ + NH_-1)*N_ + n];
    const float* sh = s_hist + ((size_t)(b*NH_ + NH_-1)*N_ + n)*3;
    scur[idx*3+0]=sh[0]; scur[idx*3+1]=sh[1]; scur[idx*3+2]=sh[2];
    float* pp = pein + (size_t)idx*16;
#pragma unroll
    for (int h=0; h<NH_; ++h) {
        const float* sd = s_delta + ((size_t)(b*NH_+h)*N_ + n)*3;
        pp[h*3+0]=sd[0]; pp[h*3+1]=sd[1]; pp[h*3+2]=sd[2];
        pp[12+h] = a_hist[(b*NH_+h)*N_ + n];
    }
}

// ---------------------------------------------------------------------------
// top-10 nearest (stable tie-break matching lax.top_k)
// ---------------------------------------------------------------------------
__global__ void topk_kernel(const float* __restrict__ scur,
                            const float* __restrict__ acur,
                            int* __restrict__ send, float* __restrict__ flag)
{
    __shared__ float sx[N_], sy[N_], sz[N_];
    __shared__ unsigned char st[N_];
    int b = blockIdx.y;
    for (int j = threadIdx.x; j < N_; j += blockDim.x) {
        int g = b*N_+j;
        sx[j]=scur[g*3+0]; sy[j]=scur[g*3+1]; sz[j]=scur[g*3+2];
        st[j] = acur[g] > 0.5f ? 1 : 0;
    }
    __syncthreads();
    int i = blockIdx.x*blockDim.x + threadIdx.x;
    if (i >= N_) return;
    bool ti = st[i] != 0;
    float xi=sx[i], yi=sy[i], zi=sz[i];
    float dv[K_TOP]; int iv[K_TOP];
#pragma unroll
    for (int t=0;t<K_TOP;++t){ dv[t]=3.0e38f; iv[t]=0; }
    for (int j=0;j<N_;++j) {
        float dx=__fadd_rn(xi,-sx[j]), dy=__fadd_rn(yi,-sy[j]), dz=__fadd_rn(zi,-sz[j]);
        float d = __fadd_rn(__fadd_rn(__fmul_rn(dx,dx),__fmul_rn(dy,dy)),__fmul_rn(dz,dz));
        if (ti && st[j]) d = 1e10f;
        if (d < dv[K_TOP-1]) {
#pragma unroll
            for (int t=K_TOP-1; t>=1; --t) {
                if (d < dv[t-1])      { dv[t]=dv[t-1]; iv[t]=iv[t-1]; }
                else if (d < dv[t])   { dv[t]=d;       iv[t]=j; }
            }
            if (d < dv[0]) { dv[0]=d; iv[0]=j; }
        }
    }
    int gi = b*N_ + i;
#pragma unroll
    for (int k=0;k<K_TOP;++k) {
        int rg = gi*K_TOP + k;
        send[rg] = b*N_ + iv[k];
        flag[rg] = (!ti && dv[k] < 0.25f) ? 1.0f : 0.0f;
    }
}

// ---------------------------------------------------------------------------
__global__ void __launch_bounds__(1024)
scan_kernel(const float* __restrict__ flag, int* __restrict__ offsets,
            int* __restrict__ Mact)
{
    __shared__ int part[1024];
    int tid = threadIdx.x;
    int local[4];
    int run = 0;
#pragma unroll
    for (int q=0;q<4;++q) {
        int node = tid*4+q;
        int c = 0;
        if (node < NODES) {
#pragma unroll
            for (int k=0;k<K_TOP;++k) c += (flag[node*K_TOP+k] != 0.f);
        }
        local[q]=run; run+=c;
    }
    part[tid]=run;
    __syncthreads();
    for (int d=1; d<1024; d<<=1) {
        int v = (tid>=d) ? part[tid-d] : 0;
        __syncthreads();
        part[tid] += v;
        __syncthreads();
    }
    int before = (tid==0) ? 0 : part[tid-1];
#pragma unroll
    for (int q=0;q<4;++q) {
        int node = tid*4+q;
        if (node < NODES) offsets[node] = before + local[q];
    }
    if (tid == 1023) { offsets[NODES] = part[1023]; Mact[0] = part[1023]; }
}

// ---------------------------------------------------------------------------
__global__ void fill_kernel(const float* __restrict__ scur, const float* __restrict__ acur,
                            const int* __restrict__ send, const float* __restrict__ flag,
                            const int* __restrict__ offsets,
                            int* __restrict__ sendc, float* __restrict__ rein)
{
    int node = blockIdx.x*blockDim.x+threadIdx.x;
    if (node >= NODES) return;
    int pos = offsets[node];
    float ar = acur[node];
    float x = scur[node*3+0], y = scur[node*3+1], z = scur[node*3+2];
#pragma unroll
    for (int k=0;k<K_TOP;++k) {
        int r = node*K_TOP+k;
        if (flag[r] != 0.f) {
            int s = send[r];
            sendc[pos] = s;
            float* o = rein + (size_t)pos*5;
            o[0] = ar;
            o[1] = acur[s];
            o[2] = x - scur[s*3+0];
            o[3] = y - scur[s*3+1];
            o[4] = z - scur[s*3+2];
            pos++;
        }
    }
}

// ---------------------------------------------------------------------------
__global__ void w23_kernel(const float* __restrict__ rp_w, float* __restrict__ w23)
{
    int idx = blockIdx.x*blockDim.x+threadIdx.x;
    if (idx >= NF_*2*NF_) return;
    int k = idx / (2*NF_), c = idx % (2*NF_);
    float v = (c < NF_) ? rp_w[(256+k)*NF_ + c] : rp_w[(512+k)*NF_ + (c-NF_)];
    w23[idx] = v;
}

// ---------------------------------------------------------------------------
// 64x64 fp32 SGEMM (small-K layers only)
// ---------------------------------------------------------------------------
__global__ void __launch_bounds__(256)
gemm64(const float* __restrict__ A, const float* __restrict__ W,
       const float* __restrict__ bias, float* __restrict__ C,
       const int* __restrict__ Mp, int Mconst, int K, int NOUT, int relu)
{
    int M = Mp ? __ldg(Mp) : Mconst;
    int bm = blockIdx.x * 64;
    if (bm >= M) return;
    int bn = blockIdx.y * 64;
    __shared__ __align__(16) float As[16][64];
    __shared__ __align__(16) float Bs[16][64];
    int tid = threadIdx.x;
    int ty = tid >> 4, tx = tid & 15;
    float acc[4][4] = {};
    int la_row = tid >> 2;
    int la_k0  = (tid & 3) * 4;

    for (int k0 = 0; k0 < K; k0 += 16) {
        int gm = bm + la_row;
#pragma unroll
        for (int q = 0; q < 4; ++q) {
            int kk = la_k0 + q;
            int gk = k0 + kk;
            As[kk][la_row] = (gm < M && gk < K) ? A[(size_t)gm * K + gk] : 0.f;
        }
#pragma unroll
        for (int q = 0; q < 4; ++q) {
            int lin = tid + q * 256;
            int kk = lin >> 6;
            int nn = lin & 63;
            int gk = k0 + kk;
            Bs[kk][nn] = (gk < K) ? W[(size_t)gk * NOUT + bn + nn] : 0.f;
        }
        __syncthreads();
#pragma unroll
        for (int kk = 0; kk < 16; ++kk) {
            float4 a4 = *(const float4*)&As[kk][ty*4];
            float4 b4 = *(const float4*)&Bs[kk][tx*4];
            float av[4] = {a4.x,a4.y,a4.z,a4.w};
            float bv[4] = {b4.x,b4.y,b4.z,b4.w};
#pragma unroll
            for (int i=0;i<4;++i)
#pragma unroll
                for (int j=0;j<4;++j)
                    acc[i][j] = fmaf(av[i], bv[j], acc[i][j]);
        }
        __syncthreads();
    }
#pragma unroll
    for (int i=0;i<4;++i) {
        int gm = bm + ty*4 + i;
        if (gm >= M) continue;
#pragma unroll
        for (int j=0;j<4;++j) {
            int gn = bn + tx*4 + j;
            float v = acc[i][j];
            if (bias) v += bias[gn];
            if (relu) v = fmaxf(v, 0.f);
            C[(size_t)gm * NOUT + gn] = v;
        }
    }
}

// ---------------------------------------------------------------------------
// tf32 tensor-core GEMM: 128x128 tile, BK=16, 8 warps (32x64 each),
// double-buffered SMEM, fused bias/add0/add1/relu epilogue, dynamic M.
// requires K % 16 == 0, NOUT % 128 == 0
// ---------------------------------------------------------------------------
#define SA 20
#define SB 136

__global__ void __launch_bounds__(256)
gemm_tc(const float* __restrict__ A, const float* __restrict__ W,
        const float* __restrict__ bias,
        const float* __restrict__ add0, const float* __restrict__ add1,
        float* __restrict__ C,
        const int* __restrict__ Mp, int Mconst, int K, int NOUT, int relu)
{
    int M = Mp ? __ldg(Mp) : Mconst;
    int bm = blockIdx.x * 128;
    if (bm >= M) return;
    int bn = blockIdx.y * 128;

    __shared__ unsigned As[2][128*SA];
    __shared__ unsigned Bs[2][16*SB];

    int tid = threadIdx.x;
    int wid = tid >> 5, lane = tid & 31;
    int gid = lane >> 2, tig = lane & 3;
    int warp_m = (wid & 3) * 32;    // 4 warps down
    int warp_n = (wid >> 2) * 64;   // 2 warps across

    float acc[2][8][4];
#pragma unroll
    for (int f=0;f<2;++f)
#pragma unroll
        for (int g=0;g<8;++g)
#pragma unroll
            for (int q=0;q<4;++q) acc[f][g][q]=0.f;

    int nk = K / 16;

#define TC_LOAD(buf, k0)                                                      \
    {                                                                         \
        _Pragma("unroll")                                                     \
        for (int i = 0; i < 2; ++i) {                                         \
            int idx = tid + i * 256;                                          \
            int row = idx >> 2, kq = (idx & 3) * 4;                           \
            int gm = bm + row;                                                \
            float4 v = make_float4(0.f,0.f,0.f,0.f);                          \
            if (gm < M) v = *(const float4*)(A + (size_t)gm * K + (k0) + kq); \
            As[buf][row*SA + kq + 0] = f2tf(v.x);                             \
            As[buf][row*SA + kq + 1] = f2tf(v.y);                             \
            As[buf][row*SA + kq + 2] = f2tf(v.z);                             \
            As[buf][row*SA + kq + 3] = f2tf(v.w);                             \
        }                                                                     \
        _Pragma("unroll")                                                     \
        for (int i = 0; i < 2; ++i) {                                         \
            int idx = tid + i * 256;                                          \
            int kk = idx >> 5, nn = (idx & 31) * 4;                           \
            float4 v = *(const float4*)(W + (size_t)((k0)+kk) * NOUT + bn + nn); \
            Bs[buf][kk*SB + nn + 0] = f2tf(v.x);                              \
            Bs[buf][kk*SB + nn + 1] = f2tf(v.y);                              \
            Bs[buf][kk*SB + nn + 2] = f2tf(v.z);                              \
            Bs[buf][kk*SB + nn + 3] = f2tf(v.w);                              \
        }                                                                     \
    }

    TC_LOAD(0, 0);
    __syncthreads();

    for (int t = 0; t < nk; ++t) {
        int cur = t & 1, nxt = cur ^ 1;
        if (t + 1 < nk) TC_LOAD(nxt, (t + 1) * 16);
#pragma unroll
        for (int ks = 0; ks < 2; ++ks) {
            int kb = ks * 8;
            unsigned a[2][4], b[8][2];
#pragma unroll
            for (int f = 0; f < 2; ++f) {
                int rb = warp_m + f*16;
                a[f][0] = As[cur][(rb+gid  )*SA + kb + tig];
                a[f][1] = As[cur][(rb+gid+8)*SA + kb + tig];
                a[f][2] = As[cur][(rb+gid  )*SA + kb + tig + 4];
                a[f][3] = As[cur][(rb+gid+8)*SA + kb + tig + 4];
            }
#pragma unroll
            for (int g = 0; g < 8; ++g) {
                int nb = warp_n + g*8;
                b[g][0] = Bs[cur][(kb+tig  )*SB + nb + gid];
                b[g][1] = Bs[cur][(kb+tig+4)*SB + nb + gid];
            }
#pragma unroll
            for (int f = 0; f < 2; ++f)
#pragma unroll
                for (int g = 0; g < 8; ++g) {
                    asm volatile(
                        "mma.sync.aligned.m16n8k8.row.col.f32.tf32.tf32.f32 "
                        "{%0,%1,%2,%3},{%4,%5,%6,%7},{%8,%9},{%0,%1,%2,%3};"
                        : "+f"(acc[f][g][0]), "+f"(acc[f][g][1]),
                          "+f"(acc[f][g][2]), "+f"(acc[f][g][3])
                        : "r"(a[f][0]), "r"(a[f][1]), "r"(a[f][2]), "r"(a[f][3]),
                          "r"(b[g][0]), "r"(b[g][1]));
                }
        }
        __syncthreads();
    }
#undef TC_LOAD

    // epilogue
#pragma unroll
    for (int f = 0; f < 2; ++f) {
        int r0 = bm + warp_m + f*16 + gid;
        int r1 = r0 + 8;
#pragma unroll
        for (int g = 0; g < 8; ++g) {
            int ccol = bn + warp_n + g*8 + tig*2;
            float b0 = bias ? bias[ccol] : 0.f;
            float b1 = bias ? bias[ccol+1] : 0.f;
            if (r0 < M) {
                size_t off = (size_t)r0 * NOUT + ccol;
                float v0 = acc[f][g][0] + b0;
                float v1 = acc[f][g][1] + b1;
                if (add0) { v0 += add0[off]; v1 += add0[off+1]; }
                if (add1) { v0 += add1[off]; v1 += add1[off+1]; }
                if (relu) { v0 = fmaxf(v0,0.f); v1 = fmaxf(v1,0.f); }
                *(float2*)(C + off) = make_float2(v0, v1);
            }
            if (r1 < M) {
                size_t off = (size_t)r1 * NOUT + ccol;
                float v0 = acc[f][g][2] + b0;
                float v1 = acc[f][g][3] + b1;
                if (add0) { v0 += add0[off]; v1 += add0[off+1]; }
                if (add1) { v0 += add1[off]; v1 += add1[off+1]; }
                if (relu) { v0 = fmaxf(v0,0.f); v1 = fmaxf(v1,0.f); }
                *(float2*)(C + off) = make_float2(v0, v1);
            }
        }
    }
}

// ---------------------------------------------------------------------------
__global__ void agg_kernel(const float* __restrict__ base, const float* __restrict__ G23,
                           const int* __restrict__ sendc, const int* __restrict__ offsets,
                           float* __restrict__ agg)
{
    int node = blockIdx.x;
    int c = threadIdx.x;
    float g2 = G23[(size_t)node*(2*NF_) + c];
    int e0 = offsets[node], e1 = offsets[node+1];
    float acc = 0.f;
    for (int e = e0; e < e1; ++e) {
        float v = base[(size_t)e*NF_ + c] + g2 + G23[(size_t)sendc[e]*(2*NF_) + NF_ + c];
        acc += fmaxf(v, 0.f);
    }
    agg[(size_t)node*NF_ + c] = acc;
}

// ---------------------------------------------------------------------------
__global__ void out_kernel(const float* __restrict__ h, const float* __restrict__ w,
                           const float* __restrict__ bias, const float* __restrict__ scur,
                           float* __restrict__ out)
{
    int e = blockIdx.x*blockDim.x+threadIdx.x;
    if (e >= NODES*3) return;
    int row = e/3, j = e%3;
    float acc = 0.f;
    const float* hr = h + (size_t)row*NF_;
#pragma unroll 8
    for (int k=0;k<NF_;++k) acc = fmaf(hr[k], w[k*3+j], acc);
    out[e] = acc + bias[j] + scur[e];
}

// ---------------------------------------------------------------------------
extern "C" void kernel_launch(void* const* d_in, const int* in_sizes, int n_in,
                              void* d_out, int out_size)
{
    const float* a_hist =(const float*)d_in[0];
    const float* s_hist =(const float*)d_in[1];
    const float* s_delta=(const float*)d_in[2];
    const float* pe_w0=(const float*)d_in[3];  const float* pe_b0=(const float*)d_in[4];
    const float* pe_w1=(const float*)d_in[5];  const float* pe_b1=(const float*)d_in[6];
    const float* re_w0=(const float*)d_in[7];  const float* re_b0=(const float*)d_in[8];
    const float* re_w1=(const float*)d_in[9];  const float* re_b1=(const float*)d_in[10];
    const float* re_w2=(const float*)d_in[11]; const float* re_b2=(const float*)d_in[12];
    const float* rp_w =(const float*)d_in[13]; const float* rp_b =(const float*)d_in[14];
    const float* pp_w =(const float*)d_in[15]; const float* pp_b =(const float*)d_in[16];
    const float* pr_w0=(const float*)d_in[17]; const float* pr_b0=(const float*)d_in[18];
    const float* pr_w1=(const float*)d_in[19]; const float* pr_b1=(const float*)d_in[20];
    float* out = (float*)d_out;

    void* sp;   cudaGetSymbolAddress(&sp, g_scratch);
    void* p1;   cudaGetSymbolAddress(&p1, g_send);
    void* p2;   cudaGetSymbolAddress(&p2, g_sendc);
    void* p3;   cudaGetSymbolAddress(&p3, g_offsets);
    void* p4;   cudaGetSymbolAddress(&p4, g_Mact);
    float* S = (float*)sp;
    int* send    = (int*)p1;
    int* sendc   = (int*)p2;
    int* offsets = (int*)p3;
    int* Mact    = (int*)p4;

    float* scur=S+OFF_SCUR; float* acur=S+OFF_ACUR; float* pein=S+OFF_PEIN;
    float* flag=S+OFF_FLAG; float* rein=S+OFF_REIN;
    float* bufA=S+OFF_BUFA; float* bufB=S+OFF_BUFB; float* base=S+OFF_BASE;
    float* peh =S+OFF_PEH;  float* pe  =S+OFF_PE;   float* G23 =S+OFF_G23;
    float* agg =S+OFF_AGG;  float* ppc =S+OFF_PPC;  float* hout=S+OFF_HOUT;
    float* w23 =S+OFF_W23;

    prep_kernel<<<(NODES+127)/128,128>>>(a_hist,s_hist,s_delta,scur,acur,pein);
    topk_kernel<<<dim3((N_+127)/128,B_),128>>>(scur,acur,send,flag);
    scan_kernel<<<1,1024>>>(flag, offsets, Mact);
    fill_kernel<<<(NODES+127)/128,128>>>(scur,acur,send,flag,offsets,sendc,rein);
    w23_kernel<<<(NF_*2*NF_+255)/256,256>>>(rp_w, w23);

    // tf32 tensor GEMM helpers
    auto TCN = [&](const float* A,const float* W,const float* bias,
                   const float* a0,const float* a1,float* C,int K,int NOUT,int relu){
        dim3 grid((NODES+127)/128, NOUT/128);
        gemm_tc<<<grid,256>>>(A,W,bias,a0,a1,C,nullptr,NODES,K,NOUT,relu);
    };
    auto TCE = [&](const float* A,const float* W,const float* bias,
                   float* C,int relu){
        dim3 grid((EDGES+127)/128, NF_/128);   // worst-case grid, early exit on Mact
        gemm_tc<<<grid,256>>>(A,W,bias,nullptr,nullptr,C,Mact,0,NF_,NF_,relu);
    };

    // particle encoder (layer0 fp32, K=16)
    {
        dim3 grid((NODES+63)/64, NF_/64);
        gemm64<<<grid,256>>>(pein, pe_w0, pe_b0, peh, nullptr, NODES, 16, NF_, 1);
    }
    TCN(peh, pe_w1, pe_b1, nullptr, nullptr, pe,  256, NF_, 1);
    TCN(pe,  pp_w,  pp_b,  nullptr, nullptr, ppc, 256, NF_, 0);   // loop-invariant

    // relation encoder on compacted edges (layer0 fp32, K=5)
    {
        dim3 grid((EDGES+63)/64, NF_/64);
        gemm64<<<grid,256>>>(rein, re_w0, re_b0, bufA, Mact, 0, 5, NF_, 1);
    }
    TCE(bufA, re_w1, re_b1, bufB, 1);
    TCE(bufB, re_w2, re_b2, bufA, 1);          // bufA = relation_encode
    TCE(bufA, rp_w,  rp_b,  base, 0);          // base = renc@rp_w[0:256]+rp_b

    for (int step=0; step<3; ++step) {
        TCN(pe, w23, nullptr, nullptr, nullptr, G23, 256, 2*NF_, 0);
        agg_kernel<<<NODES, NF_>>>(base, G23, sendc, offsets, agg);
        TCN(agg, pp_w + 256*NF_, nullptr, ppc, pe, pe, 256, NF_, 1);
    }

    TCN(pe, pr_w0, pr_b0, nullptr, nullptr, hout, 256, NF_, 1);
    out_kernel<<<(NODES*3+127)/128,128>>>(hout, pr_w1, pr_b1, scur, out);
}